// round 11
// baseline (speedup 1.0000x reference)
#include <cuda_runtime.h>
#include <cuda_bf16.h>
#include <cstdint>

#define N_NODES 100000
#define HID 256
#define DIN 128
#define E_MAX 1600000
#define SCAN_B 256
#define NB_MAX 512

// ---------------- scratch (no cudaMalloc allowed) ----------------
__device__ float g_agg [(size_t)N_NODES * HID];
__device__ float g_hid [(size_t)N_NODES * HID];
__device__ float g_agg2[(size_t)N_NODES * HID];
__device__ float g_hid2[(size_t)N_NODES * HID];
__device__ float g_xh_t[(size_t)N_NODES * DIN];
__device__ float g_xb_t[(size_t)N_NODES * DIN];
__device__ float g_wt[393216];
__device__ int   g_cnt[2 * N_NODES];
__device__ int   g_part[2 * NB_MAX];
__device__ int   g_rowptr[2 * (N_NODES + 1)];
__device__ int   g_cursor[2 * N_NODES];
__device__ int   g_adj[2 * E_MAX];

// weight scratch offsets (floats)
#define W_H1L 0
#define W_H1R 32768
#define W_H2L 65536
#define W_H2R 131072
#define W_B1L 196608
#define W_B1R 229376
#define W_B2L 262144
#define W_B2R 327680

// ---------------- tf32 helpers ----------------
__device__ __forceinline__ unsigned f2tf32(float f) {
    unsigned u;
    asm("cvt.rna.tf32.f32 %0, %1;" : "=r"(u) : "f"(f));
    return u;
}
__device__ __forceinline__ float t32(float f) { return __uint_as_float(f2tf32(f)); }

__device__ __forceinline__ void mma1688(float* c, const unsigned* a, const unsigned* b) {
    asm volatile(
        "mma.sync.aligned.m16n8k8.row.col.f32.tf32.tf32.f32 "
        "{%0,%1,%2,%3}, {%4,%5,%6,%7}, {%8,%9}, {%0,%1,%2,%3};"
        : "+f"(c[0]), "+f"(c[1]), "+f"(c[2]), "+f"(c[3])
        : "r"(a[0]), "r"(a[1]), "r"(a[2]), "r"(a[3]),
          "r"(b[0]), "r"(b[1]));
}

__device__ __forceinline__ void cp16(uint32_t smem, const void* gmem, int bytes) {
    asm volatile("cp.async.ca.shared.global [%0], [%1], 16, %2;"
                 :: "r"(smem), "l"(gmem), "r"(bytes) : "memory");
}
__device__ __forceinline__ void cp_commit() {
    asm volatile("cp.async.commit_group;" ::: "memory");
}
template <int NN>
__device__ __forceinline__ void cp_wait() {
    asm volatile("cp.async.wait_group %0;" :: "n"(NN) : "memory");
}

// ---------------- GEMM geometry ----------------
#define BM 128
#define BN 128
#define BK 16
#define AST 20
#define BST 136
#define STAGES 4
#define STG_FLTS (BM * AST + BK * BST)
#define GEMM_SMEM (STAGES * STG_FLTS * 4)

// ---------------- one-time resources (2 streams, as proven in R8) ----------
__global__ void sage_gemm_pipe(const float*, const float*, const float*, const float*,
                               const float*, float*, int, int, int);

static cudaStream_t g_s1;
static cudaEvent_t  g_ev_fork, g_ev_csr, g_ev_cvt, g_ev_join;
static bool g_par_ok = false;
namespace {
struct _Init {
    _Init() {
        bool ok = true;
        ok = ok && (cudaStreamCreateWithFlags(&g_s1, cudaStreamNonBlocking) == cudaSuccess);
        ok = ok && (cudaEventCreateWithFlags(&g_ev_fork, cudaEventDisableTiming) == cudaSuccess);
        ok = ok && (cudaEventCreateWithFlags(&g_ev_csr, cudaEventDisableTiming) == cudaSuccess);
        ok = ok && (cudaEventCreateWithFlags(&g_ev_cvt, cudaEventDisableTiming) == cudaSuccess);
        ok = ok && (cudaEventCreateWithFlags(&g_ev_join, cudaEventDisableTiming) == cudaSuccess);
        g_par_ok = ok;
        cudaFuncSetAttribute(sage_gemm_pipe, cudaFuncAttributeMaxDynamicSharedMemorySize, GEMM_SMEM);
    }
};
static _Init _init;
}

// ---------------- conversion kernels ----------------
__global__ void cvt_tf32_k(const float* __restrict__ in, float* __restrict__ outp, int n) {
    int i = blockIdx.x * blockDim.x + threadIdx.x;
    int stride = gridDim.x * blockDim.x;
    for (; i < n; i += stride) outp[i] = t32(in[i]);
}

struct CvtJob8 {
    const float* src[8];
    float*       dst[8];
    int          n[8];
};
__global__ void cvt_w8(CvtJob8 j) {
    int m = blockIdx.y;
    const float* s = j.src[m];
    float* d = j.dst[m];
    int n = j.n[m];
    int i = blockIdx.x * blockDim.x + threadIdx.x;
    int stride = gridDim.x * blockDim.x;
    for (; i < n; i += stride) d[i] = t32(s[i]);
}

// ---------------- CSR build ----------------
__global__ void count_deg(const int* __restrict__ src, const int* __restrict__ dst,
                          int* __restrict__ cnt, int E) {
    int e = blockIdx.x * blockDim.x + threadIdx.x;
    if (e < E) {
        atomicAdd(&cnt[src[e]], 1);
        atomicAdd(&cnt[N_NODES + dst[e]], 1);
    }
}

__device__ __forceinline__ int block_incl_scan256(int v, int* warpS) {
    int lane = threadIdx.x & 31, w = threadIdx.x >> 5;
#pragma unroll
    for (int o = 1; o < 32; o <<= 1) {
        int t = __shfl_up_sync(0xffffffffu, v, o);
        if (lane >= o) v += t;
    }
    if (lane == 31) warpS[w] = v;
    __syncthreads();
    if (w == 0) {
        int s = (lane < 8) ? warpS[lane] : 0;
#pragma unroll
        for (int o = 1; o < 8; o <<= 1) {
            int t = __shfl_up_sync(0xffffffffu, s, o);
            if (lane >= o) s += t;
        }
        if (lane < 8) warpS[lane] = s;
    }
    __syncthreads();
    int add = (w > 0) ? warpS[w - 1] : 0;
    return v + add;
}

__global__ void scan_reduce(const int* __restrict__ cnt, int* __restrict__ part, int n) {
    __shared__ int warpS[8];
    int dir = blockIdx.y;
    int i = blockIdx.x * SCAN_B + threadIdx.x;
    int v = (i < n) ? cnt[dir * N_NODES + i] : 0;
    int incl = block_incl_scan256(v, warpS);
    if (threadIdx.x == SCAN_B - 1) part[dir * NB_MAX + blockIdx.x] = incl;
}

__global__ void scan_top(int* __restrict__ part, int nb) {
    __shared__ int warpS[16];
    int dir = blockIdx.y;
    int lane = threadIdx.x & 31, w = threadIdx.x >> 5;
    int v = (threadIdx.x < nb) ? part[dir * NB_MAX + threadIdx.x] : 0;
    int incl = v;
#pragma unroll
    for (int o = 1; o < 32; o <<= 1) {
        int t = __shfl_up_sync(0xffffffffu, incl, o);
        if (lane >= o) incl += t;
    }
    if (lane == 31) warpS[w] = incl;
    __syncthreads();
    if (w == 0) {
        int s = (lane < 16) ? warpS[lane] : 0;
#pragma unroll
        for (int o = 1; o < 16; o <<= 1) {
            int t = __shfl_up_sync(0xffffffffu, s, o);
            if (lane >= o) s += t;
        }
        if (lane < 16) warpS[lane] = s;
    }
    __syncthreads();
    if (w > 0) incl += warpS[w - 1];
    if (threadIdx.x < nb) part[dir * NB_MAX + threadIdx.x] = incl - v;
}

__global__ void scan_write(const int* __restrict__ cnt, const int* __restrict__ part,
                           int* __restrict__ rowptr, int* __restrict__ cursor, int n, int E) {
    __shared__ int warpS[8];
    int dir = blockIdx.y;
    int i = blockIdx.x * SCAN_B + threadIdx.x;
    int v = (i < n) ? cnt[dir * N_NODES + i] : 0;
    int incl = block_incl_scan256(v, warpS);
    int ex = incl - v + part[dir * NB_MAX + blockIdx.x];
    if (i < n) {
        rowptr[dir * (N_NODES + 1) + i] = ex;
        cursor[dir * N_NODES + i] = ex;
        if (i == n - 1) rowptr[dir * (N_NODES + 1) + n] = E;
    }
}

__global__ void scatter_adj(const int* __restrict__ src, const int* __restrict__ dst,
                            int* __restrict__ cursor, int* __restrict__ adj, int E) {
    int e = blockIdx.x * blockDim.x + threadIdx.x;
    if (e < E) {
        int s = src[e], d = dst[e];
        int p0 = atomicAdd(&cursor[s], 1);
        adj[p0] = d;
        int p1 = atomicAdd(&cursor[N_NODES + d], 1);
        adj[E_MAX + p1] = s;
    }
}

// ---------------- CSR aggregation (4-edge unrolled, tf32-rounded output) ------
__global__ __launch_bounds__(256) void aggregate_csr(
    const float* __restrict__ x, const int* __restrict__ rowptr,
    const int* __restrict__ adj, float* __restrict__ agg, int Nn, int D)
{
    int node = blockIdx.x * 8 + (threadIdx.x >> 5);
    if (node >= Nn) return;
    int lane = threadIdx.x & 31;
    int p0 = __ldg(&rowptr[node]);
    int p1 = __ldg(&rowptr[node + 1]);
    int deg = p1 - p0;
    float inv = 1.0f / (float)(deg > 0 ? deg : 1);
    const bool wide = (D > 128);

    float4 a0 = make_float4(0.f, 0.f, 0.f, 0.f);
    float4 a1 = make_float4(0.f, 0.f, 0.f, 0.f);

    int p = p0;
    for (; p + 3 < p1; p += 4) {
        int g0 = __ldg(&adj[p]);
        int g1 = __ldg(&adj[p + 1]);
        int g2 = __ldg(&adj[p + 2]);
        int g3 = __ldg(&adj[p + 3]);
        const float4* r0 = (const float4*)(x + (size_t)g0 * D);
        const float4* r1 = (const float4*)(x + (size_t)g1 * D);
        const float4* r2 = (const float4*)(x + (size_t)g2 * D);
        const float4* r3 = (const float4*)(x + (size_t)g3 * D);
        float4 v0 = __ldg(&r0[lane]);
        float4 v1 = __ldg(&r1[lane]);
        float4 v2 = __ldg(&r2[lane]);
        float4 v3 = __ldg(&r3[lane]);
        a0.x += (v0.x + v1.x) + (v2.x + v3.x);
        a0.y += (v0.y + v1.y) + (v2.y + v3.y);
        a0.z += (v0.z + v1.z) + (v2.z + v3.z);
        a0.w += (v0.w + v1.w) + (v2.w + v3.w);
        if (wide) {
            float4 w0 = __ldg(&r0[lane + 32]);
            float4 w1 = __ldg(&r1[lane + 32]);
            float4 w2 = __ldg(&r2[lane + 32]);
            float4 w3 = __ldg(&r3[lane + 32]);
            a1.x += (w0.x + w1.x) + (w2.x + w3.x);
            a1.y += (w0.y + w1.y) + (w2.y + w3.y);
            a1.z += (w0.z + w1.z) + (w2.z + w3.z);
            a1.w += (w0.w + w1.w) + (w2.w + w3.w);
        }
    }
    for (; p < p1; ++p) {
        int g0 = __ldg(&adj[p]);
        const float4* r0 = (const float4*)(x + (size_t)g0 * D);
        float4 v0 = __ldg(&r0[lane]);
        a0.x += v0.x; a0.y += v0.y; a0.z += v0.z; a0.w += v0.w;
        if (wide) {
            float4 w0 = __ldg(&r0[lane + 32]);
            a1.x += w0.x; a1.y += w0.y; a1.z += w0.z; a1.w += w0.w;
        }
    }

    float4* op = (float4*)(agg + (size_t)node * D);
    a0.x = t32(a0.x * inv); a0.y = t32(a0.y * inv);
    a0.z = t32(a0.z * inv); a0.w = t32(a0.w * inv);
    op[lane] = a0;
    if (wide) {
        a1.x = t32(a1.x * inv); a1.y = t32(a1.y * inv);
        a1.z = t32(a1.z * inv); a1.w = t32(a1.w * inv);
        op[lane + 32] = a1;
    }
}

// ---------------------------------------------------------------------------
// cp.async pipelined tf32 GEMM (inputs pre-rounded to tf32 bit patterns)
// ---------------------------------------------------------------------------
__global__ __launch_bounds__(256, 2) void sage_gemm_pipe(
    const float* __restrict__ Aagg, const float* __restrict__ Ax,
    const float* __restrict__ Wl, const float* __restrict__ Wr,
    const float* __restrict__ bias, float* __restrict__ out,
    int M, int K, int cvt_out)
{
    extern __shared__ float smem[];
    const int tid  = threadIdx.x;
    const int lane = tid & 31;
    const int warp = tid >> 5;
    const int wm = (warp & 1) * 64;
    const int wn = (warp >> 1) * 32;
    const int bm = blockIdx.x * BM;
    const int bn = blockIdx.y * BN;

    uint32_t smem_u32;
    {
        uint32_t a;
        asm("{ .reg .u64 t; cvta.to.shared.u64 t, %1; cvt.u32.u64 %0, t; }"
            : "=r"(a) : "l"(smem));
        smem_u32 = a;
    }

    float acc[4][4][4];
#pragma unroll
    for (int mi = 0; mi < 4; ++mi)
#pragma unroll
        for (int ni = 0; ni < 4; ++ni)
#pragma unroll
            for (int c = 0; c < 4; ++c) acc[mi][ni][c] = 0.f;

    const int ntiles = (2 * K) / BK;

    const int ar0 = tid >> 2;
    const int ak0 = (tid & 3) << 2;
    const int bk0 = tid >> 5;
    const int bn0 = (tid & 31) << 2;

    auto load_tile = [&](int stage, int tile) {
        int kt = tile * BK;
        const float* A; const float* B; int k0;
        if (kt < K) { A = Aagg; B = Wl; k0 = kt; }
        else        { A = Ax;   B = Wr; k0 = kt - K; }
        uint32_t as_base = smem_u32 + (stage * STG_FLTS) * 4;
        uint32_t bs_base = as_base + (BM * AST) * 4;
#pragma unroll
        for (int r = 0; r < 2; ++r) {
            int row = ar0 + r * 64;
            uint32_t d = as_base + (row * AST + ak0) * 4;
            const float* s = A + (size_t)(bm + row) * K + k0 + ak0;
            cp16(d, s, (bm + row) < M ? 16 : 0);
        }
#pragma unroll
        for (int r = 0; r < 2; ++r) {
            int kr = bk0 + r * 8;
            uint32_t d = bs_base + (kr * BST + bn0) * 4;
            const float* s = B + (size_t)(k0 + kr) * HID + bn + bn0;
            cp16(d, s, 16);
        }
    };

#pragma unroll
    for (int s = 0; s < STAGES - 1; ++s) {
        load_tile(s, s);
        cp_commit();
    }
    cp_wait<STAGES - 2>();
    __syncthreads();

    const int qk = lane & 3;
    const int qr = lane >> 2;

    for (int t = 0; t < ntiles; ++t) {
        int stage = t % STAGES;
        const float* as = smem + stage * STG_FLTS;
        const float* bs = as + BM * AST;

#pragma unroll
        for (int kg = 0; kg < BK; kg += 8) {
            unsigned a[4][4], b[4][2];
#pragma unroll
            for (int mi = 0; mi < 4; ++mi) {
                int m0 = wm + mi * 16 + qr;
                a[mi][0] = __float_as_uint(as[m0 * AST + kg + qk]);
                a[mi][1] = __float_as_uint(as[(m0 + 8) * AST + kg + qk]);
                a[mi][2] = __float_as_uint(as[m0 * AST + kg + qk + 4]);
                a[mi][3] = __float_as_uint(as[(m0 + 8) * AST + kg + qk + 4]);
            }
#pragma unroll
            for (int ni = 0; ni < 4; ++ni) {
                int n0 = wn + ni * 8 + qr;
                b[ni][0] = __float_as_uint(bs[(kg + qk) * BST + n0]);
                b[ni][1] = __float_as_uint(bs[(kg + qk + 4) * BST + n0]);
            }
#pragma unroll
            for (int mi = 0; mi < 4; ++mi)
#pragma unroll
                for (int ni = 0; ni < 4; ++ni)
                    mma1688(acc[mi][ni], a[mi], b[ni]);
        }

        int nt = t + STAGES - 1;
        if (nt < ntiles) load_tile(nt % STAGES, nt);
        cp_commit();
        cp_wait<STAGES - 2>();
        __syncthreads();
    }

#pragma unroll
    for (int mi = 0; mi < 4; ++mi) {
        int r0 = bm + wm + mi * 16 + qr;
#pragma unroll
        for (int ni = 0; ni < 4; ++ni) {
            int c0 = bn + wn + ni * 8 + qk * 2;
            float bb0 = bias[c0];
            float bb1 = bias[c0 + 1];
            if (r0 < M) {
                float2 v;
                v.x = fmaxf(acc[mi][ni][0] + bb0, 0.f);
                v.y = fmaxf(acc[mi][ni][1] + bb1, 0.f);
                if (cvt_out) { v.x = t32(v.x); v.y = t32(v.y); }
                *(float2*)(out + (size_t)r0 * HID + c0) = v;
            }
            if (r0 + 8 < M) {
                float2 v;
                v.x = fmaxf(acc[mi][ni][2] + bb0, 0.f);
                v.y = fmaxf(acc[mi][ni][3] + bb1, 0.f);
                if (cvt_out) { v.x = t32(v.x); v.y = t32(v.y); }
                *(float2*)(out + (size_t)(r0 + 8) * HID + c0) = v;
            }
        }
    }
}

extern "C" void kernel_launch(void* const* d_in, const int* in_sizes, int n_in,
                              void* d_out, int out_size)
{
    const float* x_human = (const float*)d_in[0];
    const float* x_bact  = (const float*)d_in[1];
    const int*   ei      = (const int*)d_in[2];
    const float* h1_Wl = (const float*)d_in[3];
    const float* h1_Wr = (const float*)d_in[4];
    const float* h1_b  = (const float*)d_in[5];
    const float* h2_Wl = (const float*)d_in[6];
    const float* h2_Wr = (const float*)d_in[7];
    const float* h2_b  = (const float*)d_in[8];
    const float* b1_Wl = (const float*)d_in[9];
    const float* b1_Wr = (const float*)d_in[10];
    const float* b1_b  = (const float*)d_in[11];
    const float* b2_Wl = (const float*)d_in[12];
    const float* b2_Wr = (const float*)d_in[13];
    const float* b2_b  = (const float*)d_in[14];

    const int N = in_sizes[0] / DIN;      // 100000
    const int E = in_sizes[2] / 2;        // 1600000
    const int* src = ei;
    const int* dst = ei + E;

    float* out  = (float*)d_out;
    float* hout = out;
    float* bout = out + (size_t)N * HID;

    float *agg, *hid, *agg2, *hid2, *xh, *xb, *wt;
    int *cnt, *part, *rowptr, *cursor, *adj;
    cudaGetSymbolAddress((void**)&agg,    g_agg);
    cudaGetSymbolAddress((void**)&hid,    g_hid);
    cudaGetSymbolAddress((void**)&agg2,   g_agg2);
    cudaGetSymbolAddress((void**)&hid2,   g_hid2);
    cudaGetSymbolAddress((void**)&xh,     g_xh_t);
    cudaGetSymbolAddress((void**)&xb,     g_xb_t);
    cudaGetSymbolAddress((void**)&wt,     g_wt);
    cudaGetSymbolAddress((void**)&cnt,    g_cnt);
    cudaGetSymbolAddress((void**)&part,   g_part);
    cudaGetSymbolAddress((void**)&rowptr, g_rowptr);
    cudaGetSymbolAddress((void**)&cursor, g_cursor);
    cudaGetSymbolAddress((void**)&adj,    g_adj);

    const int* rp_s = rowptr;
    const int* rp_d = rowptr + (N_NODES + 1);
    const int* adj_s = adj;
    const int* adj_d = adj + E_MAX;

    const int TB = 256;
    const int nb_N = (N + TB - 1) / TB;
    const int nb_E = (E + TB - 1) / TB;
    const int nb_agg = (N * 32 + TB - 1) / TB;
    dim3 gemm_grid((N + 127) / 128, 2);
    dim3 scan_grid(nb_N, 2);
    dim3 top_grid(1, 2);
    dim3 w8_grid(32, 8);

    const bool par = g_par_ok;
    cudaStream_t sb = par ? g_s1 : (cudaStream_t)0;

    CvtJob8 jw;
    jw.src[0] = h1_Wl; jw.dst[0] = wt + W_H1L; jw.n[0] = DIN * HID;
    jw.src[1] = h1_Wr; jw.dst[1] = wt + W_H1R; jw.n[1] = DIN * HID;
    jw.src[2] = h2_Wl; jw.dst[2] = wt + W_H2L; jw.n[2] = HID * HID;
    jw.src[3] = h2_Wr; jw.dst[3] = wt + W_H2R; jw.n[3] = HID * HID;
    jw.src[4] = b1_Wl; jw.dst[4] = wt + W_B1L; jw.n[4] = DIN * HID;
    jw.src[5] = b1_Wr; jw.dst[5] = wt + W_B1R; jw.n[5] = DIN * HID;
    jw.src[6] = b2_Wl; jw.dst[6] = wt + W_B2L; jw.n[6] = HID * HID;
    jw.src[7] = b2_Wr; jw.dst[7] = wt + W_B2R; jw.n[7] = HID * HID;

    if (par) {
        cudaEventRecord(g_ev_fork, 0);
        cudaStreamWaitEvent(sb, g_ev_fork, 0);
    }

    // ---- all conversions on sb (overlap the CSR build on default) ----
    cvt_tf32_k<<<1024, TB, 0, sb>>>(x_human, xh, N * DIN);
    cvt_tf32_k<<<1024, TB, 0, sb>>>(x_bact, xb, N * DIN);
    cvt_w8<<<w8_grid, TB, 0, sb>>>(jw);
    if (par) cudaEventRecord(g_ev_cvt, sb);

    // ---- CSR build (default stream) ----
    cudaMemsetAsync(cnt, 0, 2 * N_NODES * sizeof(int));
    count_deg<<<nb_E, TB>>>(src, dst, cnt, E);
    scan_reduce<<<scan_grid, TB>>>(cnt, part, N);
    scan_top<<<top_grid, 512>>>(part, nb_N);
    scan_write<<<scan_grid, TB>>>(cnt, part, rowptr, cursor, N, E);
    scatter_adj<<<nb_E, TB>>>(src, dst, cursor, adj, E);

    if (par) {
        cudaEventRecord(g_ev_csr, 0);
        cudaStreamWaitEvent(sb, g_ev_csr, 0);                // bacterial branch needs CSR
        cudaStreamWaitEvent((cudaStream_t)0, g_ev_cvt, 0);   // human branch needs cvts
    }

    // ---- human branch (default stream) ----
    aggregate_csr<<<nb_agg, TB>>>(xh, rp_s, adj_s, agg, N, DIN);
    sage_gemm_pipe<<<gemm_grid, TB, GEMM_SMEM>>>(agg, xh, wt + W_H1L, wt + W_H1R, h1_b, hid, N, DIN, 1);
    aggregate_csr<<<nb_agg, TB>>>(hid, rp_s, adj_s, agg, N, HID);
    sage_gemm_pipe<<<gemm_grid, TB, GEMM_SMEM>>>(agg, hid, wt + W_H2L, wt + W_H2R, h2_b, hout, N, HID, 0);

    // ---- bacterial branch (stream sb) ----
    aggregate_csr<<<nb_agg, TB, 0, sb>>>(xb, rp_d, adj_d, agg2, N, DIN);
    sage_gemm_pipe<<<gemm_grid, TB, GEMM_SMEM, sb>>>(agg2, xb, wt + W_B1L, wt + W_B1R, b1_b, hid2, N, DIN, 1);
    aggregate_csr<<<nb_agg, TB, 0, sb>>>(hid2, rp_d, adj_d, agg2, N, HID);
    sage_gemm_pipe<<<gemm_grid, TB, GEMM_SMEM, sb>>>(agg2, hid2, wt + W_B2L, wt + W_B2R, b2_b, bout, N, HID, 0);

    if (par) {
        cudaEventRecord(g_ev_join, sb);
        cudaStreamWaitEvent((cudaStream_t)0, g_ev_join, 0);
    }
}

// round 12
// speedup vs baseline: 1.1978x; 1.1978x over previous
#include <cuda_runtime.h>
#include <cuda_bf16.h>
#include <cstdint>

#define N_NODES 100000
#define HID 256
#define DIN 128
#define E_MAX 1600000
#define SCAN_B 256
#define NB_MAX 512

// ---------------- scratch (no cudaMalloc allowed) ----------------
__device__ float g_agg [(size_t)N_NODES * HID];
__device__ float g_hid [(size_t)N_NODES * HID];
__device__ float g_agg2[(size_t)N_NODES * HID];
__device__ float g_hid2[(size_t)N_NODES * HID];
__device__ float g_xh_t[(size_t)N_NODES * DIN];
__device__ float g_xb_t[(size_t)N_NODES * DIN];
__device__ __nv_bfloat16 g_xh_b [(size_t)N_NODES * DIN];   // bf16 gather copies
__device__ __nv_bfloat16 g_xb_b [(size_t)N_NODES * DIN];
__device__ __nv_bfloat16 g_hid_b [(size_t)N_NODES * HID];
__device__ __nv_bfloat16 g_hid2_b[(size_t)N_NODES * HID];
__device__ float g_wt[393216];
__device__ int   g_cnt[2 * N_NODES];
__device__ int   g_part[2 * NB_MAX];
__device__ int   g_rowptr[2 * (N_NODES + 1)];
__device__ int   g_cursor[2 * N_NODES];
__device__ int   g_adj[2 * E_MAX];

// weight scratch offsets (floats)
#define W_H1L 0
#define W_H1R 32768
#define W_H2L 65536
#define W_H2R 131072
#define W_B1L 196608
#define W_B1R 229376
#define W_B2L 262144
#define W_B2R 327680

// ---------------- tf32/bf16 helpers ----------------
__device__ __forceinline__ unsigned f2tf32(float f) {
    unsigned u;
    asm("cvt.rna.tf32.f32 %0, %1;" : "=r"(u) : "f"(f));
    return u;
}
__device__ __forceinline__ float t32(float f) { return __uint_as_float(f2tf32(f)); }

__device__ __forceinline__ float2 bf2_to_f2(unsigned u) {
    __nv_bfloat162 h = *reinterpret_cast<__nv_bfloat162*>(&u);
    return __bfloat1622float2(h);
}

__device__ __forceinline__ void mma1688(float* c, const unsigned* a, const unsigned* b) {
    asm volatile(
        "mma.sync.aligned.m16n8k8.row.col.f32.tf32.tf32.f32 "
        "{%0,%1,%2,%3}, {%4,%5,%6,%7}, {%8,%9}, {%0,%1,%2,%3};"
        : "+f"(c[0]), "+f"(c[1]), "+f"(c[2]), "+f"(c[3])
        : "r"(a[0]), "r"(a[1]), "r"(a[2]), "r"(a[3]),
          "r"(b[0]), "r"(b[1]));
}

__device__ __forceinline__ void cp16(uint32_t smem, const void* gmem, int bytes) {
    asm volatile("cp.async.ca.shared.global [%0], [%1], 16, %2;"
                 :: "r"(smem), "l"(gmem), "r"(bytes) : "memory");
}
__device__ __forceinline__ void cp_commit() {
    asm volatile("cp.async.commit_group;" ::: "memory");
}
template <int NN>
__device__ __forceinline__ void cp_wait() {
    asm volatile("cp.async.wait_group %0;" :: "n"(NN) : "memory");
}

// ---------------- GEMM geometry ----------------
#define BM 128
#define BN 128
#define BK 16
#define AST 20
#define BST 136
#define STAGES 4
#define STG_FLTS (BM * AST + BK * BST)
#define GEMM_SMEM (STAGES * STG_FLTS * 4)

// ---------------- one-time resources (2 streams, proven topology) ----------
__global__ void sage_gemm_pipe(const float*, const float*, const float*, const float*,
                               const float*, float*, __nv_bfloat16*, int, int, int);

static cudaStream_t g_s1;
static cudaEvent_t  g_ev_fork, g_ev_csr, g_ev_cvt, g_ev_join;
static bool g_par_ok = false;
namespace {
struct _Init {
    _Init() {
        bool ok = true;
        ok = ok && (cudaStreamCreateWithFlags(&g_s1, cudaStreamNonBlocking) == cudaSuccess);
        ok = ok && (cudaEventCreateWithFlags(&g_ev_fork, cudaEventDisableTiming) == cudaSuccess);
        ok = ok && (cudaEventCreateWithFlags(&g_ev_csr, cudaEventDisableTiming) == cudaSuccess);
        ok = ok && (cudaEventCreateWithFlags(&g_ev_cvt, cudaEventDisableTiming) == cudaSuccess);
        ok = ok && (cudaEventCreateWithFlags(&g_ev_join, cudaEventDisableTiming) == cudaSuccess);
        g_par_ok = ok;
        cudaFuncSetAttribute(sage_gemm_pipe, cudaFuncAttributeMaxDynamicSharedMemorySize, GEMM_SMEM);
    }
};
static _Init _init;
}

// ---------------- conversion kernels ----------------
// x: write tf32-rounded fp32 (GEMM operand) AND bf16 copy (gather operand)
__global__ void cvt_x_k(const float* __restrict__ in, float* __restrict__ o32,
                        __nv_bfloat16* __restrict__ ob, int n) {
    int i = blockIdx.x * blockDim.x + threadIdx.x;
    int stride = gridDim.x * blockDim.x;
    for (; i < n; i += stride) {
        float v = in[i];
        o32[i] = t32(v);
        ob[i] = __float2bfloat16(v);
    }
}

struct CvtJob8 {
    const float* src[8];
    float*       dst[8];
    int          n[8];
};
__global__ void cvt_w8(CvtJob8 j) {
    int m = blockIdx.y;
    const float* s = j.src[m];
    float* d = j.dst[m];
    int n = j.n[m];
    int i = blockIdx.x * blockDim.x + threadIdx.x;
    int stride = gridDim.x * blockDim.x;
    for (; i < n; i += stride) d[i] = t32(s[i]);
}

// ---------------- CSR build ----------------
__global__ void count_deg(const int* __restrict__ src, const int* __restrict__ dst,
                          int* __restrict__ cnt, int E) {
    int e = blockIdx.x * blockDim.x + threadIdx.x;
    if (e < E) {
        atomicAdd(&cnt[src[e]], 1);
        atomicAdd(&cnt[N_NODES + dst[e]], 1);
    }
}

__device__ __forceinline__ int block_incl_scan256(int v, int* warpS) {
    int lane = threadIdx.x & 31, w = threadIdx.x >> 5;
#pragma unroll
    for (int o = 1; o < 32; o <<= 1) {
        int t = __shfl_up_sync(0xffffffffu, v, o);
        if (lane >= o) v += t;
    }
    if (lane == 31) warpS[w] = v;
    __syncthreads();
    if (w == 0) {
        int s = (lane < 8) ? warpS[lane] : 0;
#pragma unroll
        for (int o = 1; o < 8; o <<= 1) {
            int t = __shfl_up_sync(0xffffffffu, s, o);
            if (lane >= o) s += t;
        }
        if (lane < 8) warpS[lane] = s;
    }
    __syncthreads();
    int add = (w > 0) ? warpS[w - 1] : 0;
    return v + add;
}

__global__ void scan_reduce(const int* __restrict__ cnt, int* __restrict__ part, int n) {
    __shared__ int warpS[8];
    int dir = blockIdx.y;
    int i = blockIdx.x * SCAN_B + threadIdx.x;
    int v = (i < n) ? cnt[dir * N_NODES + i] : 0;
    int incl = block_incl_scan256(v, warpS);
    if (threadIdx.x == SCAN_B - 1) part[dir * NB_MAX + blockIdx.x] = incl;
}

__global__ void scan_top(int* __restrict__ part, int nb) {
    __shared__ int warpS[16];
    int dir = blockIdx.y;
    int lane = threadIdx.x & 31, w = threadIdx.x >> 5;
    int v = (threadIdx.x < nb) ? part[dir * NB_MAX + threadIdx.x] : 0;
    int incl = v;
#pragma unroll
    for (int o = 1; o < 32; o <<= 1) {
        int t = __shfl_up_sync(0xffffffffu, incl, o);
        if (lane >= o) incl += t;
    }
    if (lane == 31) warpS[w] = incl;
    __syncthreads();
    if (w == 0) {
        int s = (lane < 16) ? warpS[lane] : 0;
#pragma unroll
        for (int o = 1; o < 16; o <<= 1) {
            int t = __shfl_up_sync(0xffffffffu, s, o);
            if (lane >= o) s += t;
        }
        if (lane < 16) warpS[lane] = s;
    }
    __syncthreads();
    if (w > 0) incl += warpS[w - 1];
    if (threadIdx.x < nb) part[dir * NB_MAX + threadIdx.x] = incl - v;
}

__global__ void scan_write(const int* __restrict__ cnt, const int* __restrict__ part,
                           int* __restrict__ rowptr, int* __restrict__ cursor, int n, int E) {
    __shared__ int warpS[8];
    int dir = blockIdx.y;
    int i = blockIdx.x * SCAN_B + threadIdx.x;
    int v = (i < n) ? cnt[dir * N_NODES + i] : 0;
    int incl = block_incl_scan256(v, warpS);
    int ex = incl - v + part[dir * NB_MAX + blockIdx.x];
    if (i < n) {
        rowptr[dir * (N_NODES + 1) + i] = ex;
        cursor[dir * N_NODES + i] = ex;
        if (i == n - 1) rowptr[dir * (N_NODES + 1) + n] = E;
    }
}

__global__ void scatter_adj(const int* __restrict__ src, const int* __restrict__ dst,
                            int* __restrict__ cursor, int* __restrict__ adj, int E) {
    int e = blockIdx.x * blockDim.x + threadIdx.x;
    if (e < E) {
        int s = src[e], d = dst[e];
        int p0 = atomicAdd(&cursor[s], 1);
        adj[p0] = d;
        int p1 = atomicAdd(&cursor[N_NODES + d], 1);
        adj[E_MAX + p1] = s;
    }
}

// ---------------- CSR aggregation: bf16 gather, fp32 accumulate ----------------
// D=128: each lane loads uint2 (4 bf16) per neighbor row; D=256: uint4 (8 bf16).
__global__ __launch_bounds__(256) void aggregate_csr_b16(
    const __nv_bfloat16* __restrict__ xb, const int* __restrict__ rowptr,
    const int* __restrict__ adj, float* __restrict__ agg, int Nn, int D)
{
    int node = blockIdx.x * 8 + (threadIdx.x >> 5);
    if (node >= Nn) return;
    int lane = threadIdx.x & 31;
    int p0 = __ldg(&rowptr[node]);
    int p1 = __ldg(&rowptr[node + 1]);
    int deg = p1 - p0;
    float inv = 1.0f / (float)(deg > 0 ? deg : 1);

    if (D == 128) {
        float4 a0 = make_float4(0.f, 0.f, 0.f, 0.f);
        int p = p0;
        for (; p + 3 < p1; p += 4) {
            int g0 = __ldg(&adj[p]);
            int g1 = __ldg(&adj[p + 1]);
            int g2 = __ldg(&adj[p + 2]);
            int g3 = __ldg(&adj[p + 3]);
            uint2 u0 = __ldg((const uint2*)(xb + (size_t)g0 * 128) + lane);
            uint2 u1 = __ldg((const uint2*)(xb + (size_t)g1 * 128) + lane);
            uint2 u2 = __ldg((const uint2*)(xb + (size_t)g2 * 128) + lane);
            uint2 u3 = __ldg((const uint2*)(xb + (size_t)g3 * 128) + lane);
            float2 l0 = bf2_to_f2(u0.x), h0 = bf2_to_f2(u0.y);
            float2 l1 = bf2_to_f2(u1.x), h1 = bf2_to_f2(u1.y);
            float2 l2 = bf2_to_f2(u2.x), h2 = bf2_to_f2(u2.y);
            float2 l3 = bf2_to_f2(u3.x), h3 = bf2_to_f2(u3.y);
            a0.x += (l0.x + l1.x) + (l2.x + l3.x);
            a0.y += (l0.y + l1.y) + (l2.y + l3.y);
            a0.z += (h0.x + h1.x) + (h2.x + h3.x);
            a0.w += (h0.y + h1.y) + (h2.y + h3.y);
        }
        for (; p < p1; ++p) {
            int g0 = __ldg(&adj[p]);
            uint2 u0 = __ldg((const uint2*)(xb + (size_t)g0 * 128) + lane);
            float2 l0 = bf2_to_f2(u0.x), h0 = bf2_to_f2(u0.y);
            a0.x += l0.x; a0.y += l0.y; a0.z += h0.x; a0.w += h0.y;
        }
        a0.x = t32(a0.x * inv); a0.y = t32(a0.y * inv);
        a0.z = t32(a0.z * inv); a0.w = t32(a0.w * inv);
        ((float4*)(agg + (size_t)node * 128))[lane] = a0;
    } else {
        float4 a0 = make_float4(0.f, 0.f, 0.f, 0.f);
        float4 a1 = make_float4(0.f, 0.f, 0.f, 0.f);
        int p = p0;
        for (; p + 1 < p1; p += 2) {
            int g0 = __ldg(&adj[p]);
            int g1 = __ldg(&adj[p + 1]);
            uint4 u0 = __ldg((const uint4*)(xb + (size_t)g0 * 256) + lane);
            uint4 u1 = __ldg((const uint4*)(xb + (size_t)g1 * 256) + lane);
            float2 a = bf2_to_f2(u0.x), b = bf2_to_f2(u0.y);
            float2 c = bf2_to_f2(u0.z), d = bf2_to_f2(u0.w);
            float2 e = bf2_to_f2(u1.x), f = bf2_to_f2(u1.y);
            float2 g = bf2_to_f2(u1.z), h = bf2_to_f2(u1.w);
            a0.x += a.x + e.x; a0.y += a.y + e.y;
            a0.z += b.x + f.x; a0.w += b.y + f.y;
            a1.x += c.x + g.x; a1.y += c.y + g.y;
            a1.z += d.x + h.x; a1.w += d.y + h.y;
        }
        if (p < p1) {
            int g0 = __ldg(&adj[p]);
            uint4 u0 = __ldg((const uint4*)(xb + (size_t)g0 * 256) + lane);
            float2 a = bf2_to_f2(u0.x), b = bf2_to_f2(u0.y);
            float2 c = bf2_to_f2(u0.z), d = bf2_to_f2(u0.w);
            a0.x += a.x; a0.y += a.y; a0.z += b.x; a0.w += b.y;
            a1.x += c.x; a1.y += c.y; a1.z += d.x; a1.w += d.y;
        }
        a0.x = t32(a0.x * inv); a0.y = t32(a0.y * inv);
        a0.z = t32(a0.z * inv); a0.w = t32(a0.w * inv);
        a1.x = t32(a1.x * inv); a1.y = t32(a1.y * inv);
        a1.z = t32(a1.z * inv); a1.w = t32(a1.w * inv);
        float4* op = (float4*)(agg + (size_t)node * 256);
        op[2 * lane]     = a0;
        op[2 * lane + 1] = a1;
    }
}

// ---------------------------------------------------------------------------
// cp.async pipelined tf32 GEMM; optional tf32 round + bf16 shadow on store
// ---------------------------------------------------------------------------
__global__ __launch_bounds__(256, 2) void sage_gemm_pipe(
    const float* __restrict__ Aagg, const float* __restrict__ Ax,
    const float* __restrict__ Wl, const float* __restrict__ Wr,
    const float* __restrict__ bias, float* __restrict__ out,
    __nv_bfloat16* __restrict__ out_b16,
    int M, int K, int cvt_out)
{
    extern __shared__ float smem[];
    const int tid  = threadIdx.x;
    const int lane = tid & 31;
    const int warp = tid >> 5;
    const int wm = (warp & 1) * 64;
    const int wn = (warp >> 1) * 32;
    const int bm = blockIdx.x * BM;
    const int bn = blockIdx.y * BN;

    uint32_t smem_u32;
    {
        uint32_t a;
        asm("{ .reg .u64 t; cvta.to.shared.u64 t, %1; cvt.u32.u64 %0, t; }"
            : "=r"(a) : "l"(smem));
        smem_u32 = a;
    }

    float acc[4][4][4];
#pragma unroll
    for (int mi = 0; mi < 4; ++mi)
#pragma unroll
        for (int ni = 0; ni < 4; ++ni)
#pragma unroll
            for (int c = 0; c < 4; ++c) acc[mi][ni][c] = 0.f;

    const int ntiles = (2 * K) / BK;

    const int ar0 = tid >> 2;
    const int ak0 = (tid & 3) << 2;
    const int bk0 = tid >> 5;
    const int bn0 = (tid & 31) << 2;

    auto load_tile = [&](int stage, int tile) {
        int kt = tile * BK;
        const float* A; const float* B; int k0;
        if (kt < K) { A = Aagg; B = Wl; k0 = kt; }
        else        { A = Ax;   B = Wr; k0 = kt - K; }
        uint32_t as_base = smem_u32 + (stage * STG_FLTS) * 4;
        uint32_t bs_base = as_base + (BM * AST) * 4;
#pragma unroll
        for (int r = 0; r < 2; ++r) {
            int row = ar0 + r * 64;
            uint32_t d = as_base + (row * AST + ak0) * 4;
            const float* s = A + (size_t)(bm + row) * K + k0 + ak0;
            cp16(d, s, (bm + row) < M ? 16 : 0);
        }
#pragma unroll
        for (int r = 0; r < 2; ++r) {
            int kr = bk0 + r * 8;
            uint32_t d = bs_base + (kr * BST + bn0) * 4;
            const float* s = B + (size_t)(k0 + kr) * HID + bn + bn0;
            cp16(d, s, 16);
        }
    };

#pragma unroll
    for (int s = 0; s < STAGES - 1; ++s) {
        load_tile(s, s);
        cp_commit();
    }
    cp_wait<STAGES - 2>();
    __syncthreads();

    const int qk = lane & 3;
    const int qr = lane >> 2;

    for (int t = 0; t < ntiles; ++t) {
        int stage = t % STAGES;
        const float* as = smem + stage * STG_FLTS;
        const float* bs = as + BM * AST;

#pragma unroll
        for (int kg = 0; kg < BK; kg += 8) {
            unsigned a[4][4], b[4][2];
#pragma unroll
            for (int mi = 0; mi < 4; ++mi) {
                int m0 = wm + mi * 16 + qr;
                a[mi][0] = __float_as_uint(as[m0 * AST + kg + qk]);
                a[mi][1] = __float_as_uint(as[(m0 + 8) * AST + kg + qk]);
                a[mi][2] = __float_as_uint(as[m0 * AST + kg + qk + 4]);
                a[mi][3] = __float_as_uint(as[(m0 + 8) * AST + kg + qk + 4]);
            }
#pragma unroll
            for (int ni = 0; ni < 4; ++ni) {
                int n0 = wn + ni * 8 + qr;
                b[ni][0] = __float_as_uint(bs[(kg + qk) * BST + n0]);
                b[ni][1] = __float_as_uint(bs[(kg + qk + 4) * BST + n0]);
            }
#pragma unroll
            for (int mi = 0; mi < 4; ++mi)
#pragma unroll
                for (int ni = 0; ni < 4; ++ni)
                    mma1688(acc[mi][ni], a[mi], b[ni]);
        }

        int nt = t + STAGES - 1;
        if (nt < ntiles) load_tile(nt % STAGES, nt);
        cp_commit();
        cp_wait<STAGES - 2>();
        __syncthreads();
    }

#pragma unroll
    for (int mi = 0; mi < 4; ++mi) {
        int r0 = bm + wm + mi * 16 + qr;
#pragma unroll
        for (int ni = 0; ni < 4; ++ni) {
            int c0 = bn + wn + ni * 8 + qk * 2;
            float bb0 = bias[c0];
            float bb1 = bias[c0 + 1];
            if (r0 < M) {
                float2 v;
                v.x = fmaxf(acc[mi][ni][0] + bb0, 0.f);
                v.y = fmaxf(acc[mi][ni][1] + bb1, 0.f);
                if (out_b16) {
                    *(__nv_bfloat162*)(out_b16 + (size_t)r0 * HID + c0) =
                        __float22bfloat162_rn(v);
                }
                if (cvt_out) { v.x = t32(v.x); v.y = t32(v.y); }
                *(float2*)(out + (size_t)r0 * HID + c0) = v;
            }
            if (r0 + 8 < M) {
                float2 v;
                v.x = fmaxf(acc[mi][ni][2] + bb0, 0.f);
                v.y = fmaxf(acc[mi][ni][3] + bb1, 0.f);
                if (out_b16) {
                    *(__nv_bfloat162*)(out_b16 + (size_t)(r0 + 8) * HID + c0) =
                        __float22bfloat162_rn(v);
                }
                if (cvt_out) { v.x = t32(v.x); v.y = t32(v.y); }
                *(float2*)(out + (size_t)(r0 + 8) * HID + c0) = v;
            }
        }
    }
}

extern "C" void kernel_launch(void* const* d_in, const int* in_sizes, int n_in,
                              void* d_out, int out_size)
{
    const float* x_human = (const float*)d_in[0];
    const float* x_bact  = (const float*)d_in[1];
    const int*   ei      = (const int*)d_in[2];
    const float* h1_Wl = (const float*)d_in[3];
    const float* h1_Wr = (const float*)d_in[4];
    const float* h1_b  = (const float*)d_in[5];
    const float* h2_Wl = (const float*)d_in[6];
    const float* h2_Wr = (const float*)d_in[7];
    const float* h2_b  = (const float*)d_in[8];
    const float* b1_Wl = (const float*)d_in[9];
    const float* b1_Wr = (const float*)d_in[10];
    const float* b1_b  = (const float*)d_in[11];
    const float* b2_Wl = (const float*)d_in[12];
    const float* b2_Wr = (const float*)d_in[13];
    const float* b2_b  = (const float*)d_in[14];

    const int N = in_sizes[0] / DIN;      // 100000
    const int E = in_sizes[2] / 2;        // 1600000
    const int* src = ei;
    const int* dst = ei + E;

    float* out  = (float*)d_out;
    float* hout = out;
    float* bout = out + (size_t)N * HID;

    float *agg, *hid, *agg2, *hid2, *xh, *xb, *wt;
    __nv_bfloat16 *xhb, *xbb, *hidb, *hid2b;
    int *cnt, *part, *rowptr, *cursor, *adj;
    cudaGetSymbolAddress((void**)&agg,    g_agg);
    cudaGetSymbolAddress((void**)&hid,    g_hid);
    cudaGetSymbolAddress((void**)&agg2,   g_agg2);
    cudaGetSymbolAddress((void**)&hid2,   g_hid2);
    cudaGetSymbolAddress((void**)&xh,     g_xh_t);
    cudaGetSymbolAddress((void**)&xb,     g_xb_t);
    cudaGetSymbolAddress((void**)&xhb,    g_xh_b);
    cudaGetSymbolAddress((void**)&xbb,    g_xb_b);
    cudaGetSymbolAddress((void**)&hidb,   g_hid_b);
    cudaGetSymbolAddress((void**)&hid2b,  g_hid2_b);
    cudaGetSymbolAddress((void**)&wt,     g_wt);
    cudaGetSymbolAddress((void**)&cnt,    g_cnt);
    cudaGetSymbolAddress((void**)&part,   g_part);
    cudaGetSymbolAddress((void**)&rowptr, g_rowptr);
    cudaGetSymbolAddress((void**)&cursor, g_cursor);
    cudaGetSymbolAddress((void**)&adj,    g_adj);

    const int* rp_s = rowptr;
    const int* rp_d = rowptr + (N_NODES + 1);
    const int* adj_s = adj;
    const int* adj_d = adj + E_MAX;

    const int TB = 256;
    const int nb_N = (N + TB - 1) / TB;
    const int nb_E = (E + TB - 1) / TB;
    const int nb_agg = (N * 32 + TB - 1) / TB;
    dim3 gemm_grid((N + 127) / 128, 2);
    dim3 scan_grid(nb_N, 2);
    dim3 top_grid(1, 2);
    dim3 w8_grid(32, 8);

    const bool par = g_par_ok;
    cudaStream_t sb = par ? g_s1 : (cudaStream_t)0;

    CvtJob8 jw;
    jw.src[0] = h1_Wl; jw.dst[0] = wt + W_H1L; jw.n[0] = DIN * HID;
    jw.src[1] = h1_Wr; jw.dst[1] = wt + W_H1R; jw.n[1] = DIN * HID;
    jw.src[2] = h2_Wl; jw.dst[2] = wt + W_H2L; jw.n[2] = HID * HID;
    jw.src[3] = h2_Wr; jw.dst[3] = wt + W_H2R; jw.n[3] = HID * HID;
    jw.src[4] = b1_Wl; jw.dst[4] = wt + W_B1L; jw.n[4] = DIN * HID;
    jw.src[5] = b1_Wr; jw.dst[5] = wt + W_B1R; jw.n[5] = DIN * HID;
    jw.src[6] = b2_Wl; jw.dst[6] = wt + W_B2L; jw.n[6] = HID * HID;
    jw.src[7] = b2_Wr; jw.dst[7] = wt + W_B2R; jw.n[7] = HID * HID;

    if (par) {
        cudaEventRecord(g_ev_fork, 0);
        cudaStreamWaitEvent(sb, g_ev_fork, 0);
    }

    // ---- conversions on sb (overlap the CSR build on default) ----
    cvt_x_k<<<1024, TB, 0, sb>>>(x_human, xh, xhb, N * DIN);
    cvt_x_k<<<1024, TB, 0, sb>>>(x_bact, xb, xbb, N * DIN);
    cvt_w8<<<w8_grid, TB, 0, sb>>>(jw);
    if (par) cudaEventRecord(g_ev_cvt, sb);

    // ---- CSR build (default stream) ----
    cudaMemsetAsync(cnt, 0, 2 * N_NODES * sizeof(int));
    count_deg<<<nb_E, TB>>>(src, dst, cnt, E);
    scan_reduce<<<scan_grid, TB>>>(cnt, part, N);
    scan_top<<<top_grid, 512>>>(part, nb_N);
    scan_write<<<scan_grid, TB>>>(cnt, part, rowptr, cursor, N, E);
    scatter_adj<<<nb_E, TB>>>(src, dst, cursor, adj, E);

    if (par) {
        cudaEventRecord(g_ev_csr, 0);
        cudaStreamWaitEvent(sb, g_ev_csr, 0);                // bacterial branch needs CSR
        cudaStreamWaitEvent((cudaStream_t)0, g_ev_cvt, 0);   // human branch needs cvts
    }

    // ---- human branch (default stream) ----
    aggregate_csr_b16<<<nb_agg, TB>>>(xhb, rp_s, adj_s, agg, N, DIN);
    sage_gemm_pipe<<<gemm_grid, TB, GEMM_SMEM>>>(agg, xh, wt + W_H1L, wt + W_H1R, h1_b,
                                                 hid, hidb, N, DIN, 1);
    aggregate_csr_b16<<<nb_agg, TB>>>(hidb, rp_s, adj_s, agg, N, HID);
    sage_gemm_pipe<<<gemm_grid, TB, GEMM_SMEM>>>(agg, hid, wt + W_H2L, wt + W_H2R, h2_b,
                                                 hout, (__nv_bfloat16*)nullptr, N, HID, 0);

    // ---- bacterial branch (stream sb) ----
    aggregate_csr_b16<<<nb_agg, TB, 0, sb>>>(xbb, rp_d, adj_d, agg2, N, DIN);
    sage_gemm_pipe<<<gemm_grid, TB, GEMM_SMEM, sb>>>(agg2, xb, wt + W_B1L, wt + W_B1R, b1_b,
                                                     hid2, hid2b, N, DIN, 1);
    aggregate_csr_b16<<<nb_agg, TB, 0, sb>>>(hid2b, rp_d, adj_d, agg2, N, HID);
    sage_gemm_pipe<<<gemm_grid, TB, GEMM_SMEM, sb>>>(agg2, hid2, wt + W_B2L, wt + W_B2R, b2_b,
                                                     bout, (__nv_bfloat16*)nullptr, N, HID, 0);

    if (par) {
        cudaEventRecord(g_ev_join, sb);
        cudaStreamWaitEvent((cudaStream_t)0, g_ev_join, 0);
    }
}

// round 13
// speedup vs baseline: 1.2820x; 1.0703x over previous
#include <cuda_runtime.h>
#include <cuda_bf16.h>
#include <cstdint>

#define N_NODES 100000
#define HID 256
#define DIN 128
#define E_MAX 1600000
#define SCAN_B 256
#define NB_MAX 512

// ---------------- scratch (no cudaMalloc allowed) ----------------
__device__ float g_agg [(size_t)N_NODES * HID];
__device__ float g_hid [(size_t)N_NODES * HID];
__device__ float g_agg2[(size_t)N_NODES * HID];
__device__ float g_hid2[(size_t)N_NODES * HID];
__device__ float g_xh_t[(size_t)N_NODES * DIN];
__device__ float g_xb_t[(size_t)N_NODES * DIN];
__device__ __nv_bfloat16 g_xh_b [(size_t)N_NODES * DIN];
__device__ __nv_bfloat16 g_xb_b [(size_t)N_NODES * DIN];
__device__ __nv_bfloat16 g_hid_b [(size_t)N_NODES * HID];
__device__ __nv_bfloat16 g_hid2_b[(size_t)N_NODES * HID];
__device__ float g_wt[393216];
__device__ int   g_cnt[2 * N_NODES];
__device__ int   g_part[2 * NB_MAX];
__device__ int   g_rowptr[2 * (N_NODES + 1)];
__device__ int   g_cursor[2 * N_NODES];
__device__ int   g_adj[2 * E_MAX];

// weight scratch offsets (floats)
#define W_H1L 0
#define W_H1R 32768
#define W_H2L 65536
#define W_H2R 131072
#define W_B1L 196608
#define W_B1R 229376
#define W_B2L 262144
#define W_B2R 327680

// ---------------- tf32/bf16 helpers ----------------
__device__ __forceinline__ unsigned f2tf32(float f) {
    unsigned u;
    asm("cvt.rna.tf32.f32 %0, %1;" : "=r"(u) : "f"(f));
    return u;
}
__device__ __forceinline__ float t32(float f) { return __uint_as_float(f2tf32(f)); }

__device__ __forceinline__ float2 bf2_to_f2(unsigned u) {
    __nv_bfloat162 h = *reinterpret_cast<__nv_bfloat162*>(&u);
    return __bfloat1622float2(h);
}

__device__ __forceinline__ void mma1688(float* c, const unsigned* a, const unsigned* b) {
    asm volatile(
        "mma.sync.aligned.m16n8k8.row.col.f32.tf32.tf32.f32 "
        "{%0,%1,%2,%3}, {%4,%5,%6,%7}, {%8,%9}, {%0,%1,%2,%3};"
        : "+f"(c[0]), "+f"(c[1]), "+f"(c[2]), "+f"(c[3])
        : "r"(a[0]), "r"(a[1]), "r"(a[2]), "r"(a[3]),
          "r"(b[0]), "r"(b[1]));
}

__device__ __forceinline__ void cp16(uint32_t smem, const void* gmem, int bytes) {
    asm volatile("cp.async.ca.shared.global [%0], [%1], 16, %2;"
                 :: "r"(smem), "l"(gmem), "r"(bytes) : "memory");
}
__device__ __forceinline__ void cp_commit() {
    asm volatile("cp.async.commit_group;" ::: "memory");
}
template <int NN>
__device__ __forceinline__ void cp_wait() {
    asm volatile("cp.async.wait_group %0;" :: "n"(NN) : "memory");
}

// ---------------- GEMM geometry ----------------
#define BM 128
#define BN 128
#define BK 16
#define AST 20
#define BST 136
#define STAGES 4
#define STG_FLTS (BM * AST + BK * BST)
#define GEMM_SMEM (STAGES * STG_FLTS * 4)

// ---------------- one-time resources (2 streams, proven topology) ----------
__global__ void sage_gemm_pipe(const float*, const float*, const float*, const float*,
                               const float*, float*, __nv_bfloat16*, int, int, int);

static cudaStream_t g_s1;
static cudaEvent_t  g_ev_fork, g_ev_csr, g_ev_cvt, g_ev_join;
static bool g_par_ok = false;
namespace {
struct _Init {
    _Init() {
        bool ok = true;
        ok = ok && (cudaStreamCreateWithFlags(&g_s1, cudaStreamNonBlocking) == cudaSuccess);
        ok = ok && (cudaEventCreateWithFlags(&g_ev_fork, cudaEventDisableTiming) == cudaSuccess);
        ok = ok && (cudaEventCreateWithFlags(&g_ev_csr, cudaEventDisableTiming) == cudaSuccess);
        ok = ok && (cudaEventCreateWithFlags(&g_ev_cvt, cudaEventDisableTiming) == cudaSuccess);
        ok = ok && (cudaEventCreateWithFlags(&g_ev_join, cudaEventDisableTiming) == cudaSuccess);
        g_par_ok = ok;
        cudaFuncSetAttribute(sage_gemm_pipe, cudaFuncAttributeMaxDynamicSharedMemorySize, GEMM_SMEM);
    }
};
static _Init _init;
}

// ---------------- conversion kernels ----------------
__global__ void cvt_x_k(const float* __restrict__ in, float* __restrict__ o32,
                        __nv_bfloat16* __restrict__ ob, int n) {
    int i = blockIdx.x * blockDim.x + threadIdx.x;
    int stride = gridDim.x * blockDim.x;
    for (; i < n; i += stride) {
        float v = in[i];
        o32[i] = t32(v);
        ob[i] = __float2bfloat16(v);
    }
}

struct CvtJob8 {
    const float* src[8];
    float*       dst[8];
    int          n[8];
};
__global__ void cvt_w8(CvtJob8 j) {
    int m = blockIdx.y;
    const float* s = j.src[m];
    float* d = j.dst[m];
    int n = j.n[m];
    int i = blockIdx.x * blockDim.x + threadIdx.x;
    int stride = gridDim.x * blockDim.x;
    for (; i < n; i += stride) d[i] = t32(s[i]);
}

// ---------------- CSR build ----------------
__global__ void count_deg(const int* __restrict__ src, const int* __restrict__ dst,
                          int* __restrict__ cnt, int E) {
    int e = blockIdx.x * blockDim.x + threadIdx.x;
    if (e < E) {
        atomicAdd(&cnt[src[e]], 1);
        atomicAdd(&cnt[N_NODES + dst[e]], 1);
    }
}

__device__ __forceinline__ int block_incl_scan256(int v, int* warpS) {
    int lane = threadIdx.x & 31, w = threadIdx.x >> 5;
#pragma unroll
    for (int o = 1; o < 32; o <<= 1) {
        int t = __shfl_up_sync(0xffffffffu, v, o);
        if (lane >= o) v += t;
    }
    if (lane == 31) warpS[w] = v;
    __syncthreads();
    if (w == 0) {
        int s = (lane < 8) ? warpS[lane] : 0;
#pragma unroll
        for (int o = 1; o < 8; o <<= 1) {
            int t = __shfl_up_sync(0xffffffffu, s, o);
            if (lane >= o) s += t;
        }
        if (lane < 8) warpS[lane] = s;
    }
    __syncthreads();
    int add = (w > 0) ? warpS[w - 1] : 0;
    return v + add;
}

__global__ void scan_reduce(const int* __restrict__ cnt, int* __restrict__ part, int n) {
    __shared__ int warpS[8];
    int dir = blockIdx.y;
    int i = blockIdx.x * SCAN_B + threadIdx.x;
    int v = (i < n) ? cnt[dir * N_NODES + i] : 0;
    int incl = block_incl_scan256(v, warpS);
    if (threadIdx.x == SCAN_B - 1) part[dir * NB_MAX + blockIdx.x] = incl;
}

__global__ void scan_top(int* __restrict__ part, int nb) {
    __shared__ int warpS[16];
    int dir = blockIdx.y;
    int lane = threadIdx.x & 31, w = threadIdx.x >> 5;
    int v = (threadIdx.x < nb) ? part[dir * NB_MAX + threadIdx.x] : 0;
    int incl = v;
#pragma unroll
    for (int o = 1; o < 32; o <<= 1) {
        int t = __shfl_up_sync(0xffffffffu, incl, o);
        if (lane >= o) incl += t;
    }
    if (lane == 31) warpS[w] = incl;
    __syncthreads();
    if (w == 0) {
        int s = (lane < 16) ? warpS[lane] : 0;
#pragma unroll
        for (int o = 1; o < 16; o <<= 1) {
            int t = __shfl_up_sync(0xffffffffu, s, o);
            if (lane >= o) s += t;
        }
        if (lane < 16) warpS[lane] = s;
    }
    __syncthreads();
    if (w > 0) incl += warpS[w - 1];
    if (threadIdx.x < nb) part[dir * NB_MAX + threadIdx.x] = incl - v;
}

__global__ void scan_write(const int* __restrict__ cnt, const int* __restrict__ part,
                           int* __restrict__ rowptr, int* __restrict__ cursor, int n, int E) {
    __shared__ int warpS[8];
    int dir = blockIdx.y;
    int i = blockIdx.x * SCAN_B + threadIdx.x;
    int v = (i < n) ? cnt[dir * N_NODES + i] : 0;
    int incl = block_incl_scan256(v, warpS);
    int ex = incl - v + part[dir * NB_MAX + blockIdx.x];
    if (i < n) {
        rowptr[dir * (N_NODES + 1) + i] = ex;
        cursor[dir * N_NODES + i] = ex;
        if (i == n - 1) rowptr[dir * (N_NODES + 1) + n] = E;
    }
}

__global__ void scatter_adj(const int* __restrict__ src, const int* __restrict__ dst,
                            int* __restrict__ cursor, int* __restrict__ adj, int E) {
    int e = blockIdx.x * blockDim.x + threadIdx.x;
    if (e < E) {
        int s = src[e], d = dst[e];
        int p0 = atomicAdd(&cursor[s], 1);
        adj[p0] = d;
        int p1 = atomicAdd(&cursor[N_NODES + d], 1);
        adj[E_MAX + p1] = s;
    }
}

// ---------------- CSR aggregation: bf16 gather, fp32 accumulate ----------------
__global__ __launch_bounds__(256) void aggregate_csr_b16(
    const __nv_bfloat16* __restrict__ xb, const int* __restrict__ rowptr,
    const int* __restrict__ adj, float* __restrict__ agg, int Nn, int D)
{
    int node = blockIdx.x * 8 + (threadIdx.x >> 5);
    if (node >= Nn) return;
    int lane = threadIdx.x & 31;
    int p0 = __ldg(&rowptr[node]);
    int p1 = __ldg(&rowptr[node + 1]);
    int deg = p1 - p0;
    float inv = 1.0f / (float)(deg > 0 ? deg : 1);

    if (D == 128) {
        float4 a0 = make_float4(0.f, 0.f, 0.f, 0.f);
        int p = p0;
        for (; p + 3 < p1; p += 4) {
            int g0 = __ldg(&adj[p]);
            int g1 = __ldg(&adj[p + 1]);
            int g2 = __ldg(&adj[p + 2]);
            int g3 = __ldg(&adj[p + 3]);
            uint2 u0 = __ldg((const uint2*)(xb + (size_t)g0 * 128) + lane);
            uint2 u1 = __ldg((const uint2*)(xb + (size_t)g1 * 128) + lane);
            uint2 u2 = __ldg((const uint2*)(xb + (size_t)g2 * 128) + lane);
            uint2 u3 = __ldg((const uint2*)(xb + (size_t)g3 * 128) + lane);
            float2 l0 = bf2_to_f2(u0.x), h0 = bf2_to_f2(u0.y);
            float2 l1 = bf2_to_f2(u1.x), h1 = bf2_to_f2(u1.y);
            float2 l2 = bf2_to_f2(u2.x), h2 = bf2_to_f2(u2.y);
            float2 l3 = bf2_to_f2(u3.x), h3 = bf2_to_f2(u3.y);
            a0.x += (l0.x + l1.x) + (l2.x + l3.x);
            a0.y += (l0.y + l1.y) + (l2.y + l3.y);
            a0.z += (h0.x + h1.x) + (h2.x + h3.x);
            a0.w += (h0.y + h1.y) + (h2.y + h3.y);
        }
        for (; p < p1; ++p) {
            int g0 = __ldg(&adj[p]);
            uint2 u0 = __ldg((const uint2*)(xb + (size_t)g0 * 128) + lane);
            float2 l0 = bf2_to_f2(u0.x), h0 = bf2_to_f2(u0.y);
            a0.x += l0.x; a0.y += l0.y; a0.z += h0.x; a0.w += h0.y;
        }
        a0.x = t32(a0.x * inv); a0.y = t32(a0.y * inv);
        a0.z = t32(a0.z * inv); a0.w = t32(a0.w * inv);
        ((float4*)(agg + (size_t)node * 128))[lane] = a0;
    } else {
        float4 a0 = make_float4(0.f, 0.f, 0.f, 0.f);
        float4 a1 = make_float4(0.f, 0.f, 0.f, 0.f);
        int p = p0;
        for (; p + 1 < p1; p += 2) {
            int g0 = __ldg(&adj[p]);
            int g1 = __ldg(&adj[p + 1]);
            uint4 u0 = __ldg((const uint4*)(xb + (size_t)g0 * 256) + lane);
            uint4 u1 = __ldg((const uint4*)(xb + (size_t)g1 * 256) + lane);
            float2 a = bf2_to_f2(u0.x), b = bf2_to_f2(u0.y);
            float2 c = bf2_to_f2(u0.z), d = bf2_to_f2(u0.w);
            float2 e = bf2_to_f2(u1.x), f = bf2_to_f2(u1.y);
            float2 g = bf2_to_f2(u1.z), h = bf2_to_f2(u1.w);
            a0.x += a.x + e.x; a0.y += a.y + e.y;
            a0.z += b.x + f.x; a0.w += b.y + f.y;
            a1.x += c.x + g.x; a1.y += c.y + g.y;
            a1.z += d.x + h.x; a1.w += d.y + h.y;
        }
        if (p < p1) {
            int g0 = __ldg(&adj[p]);
            uint4 u0 = __ldg((const uint4*)(xb + (size_t)g0 * 256) + lane);
            float2 a = bf2_to_f2(u0.x), b = bf2_to_f2(u0.y);
            float2 c = bf2_to_f2(u0.z), d = bf2_to_f2(u0.w);
            a0.x += a.x; a0.y += a.y; a0.z += b.x; a0.w += b.y;
            a1.x += c.x; a1.y += c.y; a1.z += d.x; a1.w += d.y;
        }
        a0.x = t32(a0.x * inv); a0.y = t32(a0.y * inv);
        a0.z = t32(a0.z * inv); a0.w = t32(a0.w * inv);
        a1.x = t32(a1.x * inv); a1.y = t32(a1.y * inv);
        a1.z = t32(a1.z * inv); a1.w = t32(a1.w * inv);
        float4* op = (float4*)(agg + (size_t)node * 256);
        op[2 * lane]     = a0;
        op[2 * lane + 1] = a1;
    }
}

// ---------------------------------------------------------------------------
// cp.async pipelined tf32 GEMM — 4 warps, 64x64 warp tiles (min crossbar traffic)
// grid = (BN tiles, BM tiles) so column-pair CTAs share A-panel in L2.
// ---------------------------------------------------------------------------
__global__ __launch_bounds__(128, 2) void sage_gemm_pipe(
    const float* __restrict__ Aagg, const float* __restrict__ Ax,
    const float* __restrict__ Wl, const float* __restrict__ Wr,
    const float* __restrict__ bias, float* __restrict__ out,
    __nv_bfloat16* __restrict__ out_b16,
    int M, int K, int cvt_out)
{
    extern __shared__ float smem[];
    const int tid  = threadIdx.x;
    const int lane = tid & 31;
    const int warp = tid >> 5;           // 0..3
    const int wm = (warp & 1) * 64;
    const int wn = (warp >> 1) * 64;
    const int bm = blockIdx.y * BM;
    const int bn = blockIdx.x * BN;

    uint32_t smem_u32;
    {
        uint32_t a;
        asm("{ .reg .u64 t; cvta.to.shared.u64 t, %1; cvt.u32.u64 %0, t; }"
            : "=r"(a) : "l"(smem));
        smem_u32 = a;
    }

    float acc[4][8][4];
#pragma unroll
    for (int mi = 0; mi < 4; ++mi)
#pragma unroll
        for (int ni = 0; ni < 8; ++ni)
#pragma unroll
            for (int c = 0; c < 4; ++c) acc[mi][ni][c] = 0.f;

    const int ntiles = (2 * K) / BK;

    // cp.async geometry (128 threads)
    const int ar0 = tid >> 2;                 // 0..31; rows ar0 + 32r
    const int ak0 = (tid & 3) << 2;           // k offset 0/4/8/12
    const int bk0 = tid >> 5;                 // 0..3; k rows bk0 + 4r
    const int bn0 = (tid & 31) << 2;          // n offset

    auto load_tile = [&](int stage, int tile) {
        int kt = tile * BK;
        const float* A; const float* B; int k0;
        if (kt < K) { A = Aagg; B = Wl; k0 = kt; }
        else        { A = Ax;   B = Wr; k0 = kt - K; }
        uint32_t as_base = smem_u32 + (stage * STG_FLTS) * 4;
        uint32_t bs_base = as_base + (BM * AST) * 4;
#pragma unroll
        for (int r = 0; r < 4; ++r) {
            int row = ar0 + r * 32;
            uint32_t d = as_base + (row * AST + ak0) * 4;
            const float* s = A + (size_t)(bm + row) * K + k0 + ak0;
            cp16(d, s, (bm + row) < M ? 16 : 0);
        }
#pragma unroll
        for (int r = 0; r < 4; ++r) {
            int kr = bk0 + r * 4;
            uint32_t d = bs_base + (kr * BST + bn0) * 4;
            const float* s = B + (size_t)(k0 + kr) * HID + bn + bn0;
            cp16(d, s, 16);
        }
    };

#pragma unroll
    for (int s = 0; s < STAGES - 1; ++s) {
        load_tile(s, s);
        cp_commit();
    }
    cp_wait<STAGES - 2>();
    __syncthreads();

    const int qk = lane & 3;
    const int qr = lane >> 2;

    for (int t = 0; t < ntiles; ++t) {
        int stage = t % STAGES;
        const float* as = smem + stage * STG_FLTS;
        const float* bs = as + BM * AST;

#pragma unroll
        for (int kg = 0; kg < BK; kg += 8) {
            unsigned a[4][4], b[8][2];
#pragma unroll
            for (int mi = 0; mi < 4; ++mi) {
                int m0 = wm + mi * 16 + qr;
                a[mi][0] = __float_as_uint(as[m0 * AST + kg + qk]);
                a[mi][1] = __float_as_uint(as[(m0 + 8) * AST + kg + qk]);
                a[mi][2] = __float_as_uint(as[m0 * AST + kg + qk + 4]);
                a[mi][3] = __float_as_uint(as[(m0 + 8) * AST + kg + qk + 4]);
            }
#pragma unroll
            for (int ni = 0; ni < 8; ++ni) {
                int n0 = wn + ni * 8 + qr;
                b[ni][0] = __float_as_uint(bs[(kg + qk) * BST + n0]);
                b[ni][1] = __float_as_uint(bs[(kg + qk + 4) * BST + n0]);
            }
#pragma unroll
            for (int mi = 0; mi < 4; ++mi)
#pragma unroll
                for (int ni = 0; ni < 8; ++ni)
                    mma1688(acc[mi][ni], a[mi], b[ni]);
        }

        int nt = t + STAGES - 1;
        if (nt < ntiles) load_tile(nt % STAGES, nt);
        cp_commit();
        cp_wait<STAGES - 2>();
        __syncthreads();
    }

#pragma unroll
    for (int mi = 0; mi < 4; ++mi) {
        int r0 = bm + wm + mi * 16 + qr;
#pragma unroll
        for (int ni = 0; ni < 8; ++ni) {
            int c0 = bn + wn + ni * 8 + qk * 2;
            float bb0 = bias[c0];
            float bb1 = bias[c0 + 1];
            if (r0 < M) {
                float2 v;
                v.x = fmaxf(acc[mi][ni][0] + bb0, 0.f);
                v.y = fmaxf(acc[mi][ni][1] + bb1, 0.f);
                if (out_b16) {
                    *(__nv_bfloat162*)(out_b16 + (size_t)r0 * HID + c0) =
                        __float22bfloat162_rn(v);
                }
                if (cvt_out) { v.x = t32(v.x); v.y = t32(v.y); }
                *(float2*)(out + (size_t)r0 * HID + c0) = v;
            }
            if (r0 + 8 < M) {
                float2 v;
                v.x = fmaxf(acc[mi][ni][2] + bb0, 0.f);
                v.y = fmaxf(acc[mi][ni][3] + bb1, 0.f);
                if (out_b16) {
                    *(__nv_bfloat162*)(out_b16 + (size_t)(r0 + 8) * HID + c0) =
                        __float22bfloat162_rn(v);
                }
                if (cvt_out) { v.x = t32(v.x); v.y = t32(v.y); }
                *(float2*)(out + (size_t)(r0 + 8) * HID + c0) = v;
            }
        }
    }
}

extern "C" void kernel_launch(void* const* d_in, const int* in_sizes, int n_in,
                              void* d_out, int out_size)
{
    const float* x_human = (const float*)d_in[0];
    const float* x_bact  = (const float*)d_in[1];
    const int*   ei      = (const int*)d_in[2];
    const float* h1_Wl = (const float*)d_in[3];
    const float* h1_Wr = (const float*)d_in[4];
    const float* h1_b  = (const float*)d_in[5];
    const float* h2_Wl = (const float*)d_in[6];
    const float* h2_Wr = (const float*)d_in[7];
    const float* h2_b  = (const float*)d_in[8];
    const float* b1_Wl = (const float*)d_in[9];
    const float* b1_Wr = (const float*)d_in[10];
    const float* b1_b  = (const float*)d_in[11];
    const float* b2_Wl = (const float*)d_in[12];
    const float* b2_Wr = (const float*)d_in[13];
    const float* b2_b  = (const float*)d_in[14];

    const int N = in_sizes[0] / DIN;      // 100000
    const int E = in_sizes[2] / 2;        // 1600000
    const int* src = ei;
    const int* dst = ei + E;

    float* out  = (float*)d_out;
    float* hout = out;
    float* bout = out + (size_t)N * HID;

    float *agg, *hid, *agg2, *hid2, *xh, *xb, *wt;
    __nv_bfloat16 *xhb, *xbb, *hidb, *hid2b;
    int *cnt, *part, *rowptr, *cursor, *adj;
    cudaGetSymbolAddress((void**)&agg,    g_agg);
    cudaGetSymbolAddress((void**)&hid,    g_hid);
    cudaGetSymbolAddress((void**)&agg2,   g_agg2);
    cudaGetSymbolAddress((void**)&hid2,   g_hid2);
    cudaGetSymbolAddress((void**)&xh,     g_xh_t);
    cudaGetSymbolAddress((void**)&xb,     g_xb_t);
    cudaGetSymbolAddress((void**)&xhb,    g_xh_b);
    cudaGetSymbolAddress((void**)&xbb,    g_xb_b);
    cudaGetSymbolAddress((void**)&hidb,   g_hid_b);
    cudaGetSymbolAddress((void**)&hid2b,  g_hid2_b);
    cudaGetSymbolAddress((void**)&wt,     g_wt);
    cudaGetSymbolAddress((void**)&cnt,    g_cnt);
    cudaGetSymbolAddress((void**)&part,   g_part);
    cudaGetSymbolAddress((void**)&rowptr, g_rowptr);
    cudaGetSymbolAddress((void**)&cursor, g_cursor);
    cudaGetSymbolAddress((void**)&adj,    g_adj);

    const int* rp_s = rowptr;
    const int* rp_d = rowptr + (N_NODES + 1);
    const int* adj_s = adj;
    const int* adj_d = adj + E_MAX;

    const int TB = 256;
    const int nb_N = (N + TB - 1) / TB;
    const int nb_E = (E + TB - 1) / TB;
    const int nb_agg = (N * 32 + TB - 1) / TB;
    dim3 gemm_grid(2, (N + 127) / 128);   // column tiles fastest -> A-panel L2 reuse
    dim3 scan_grid(nb_N, 2);
    dim3 top_grid(1, 2);
    dim3 w8_grid(32, 8);

    const bool par = g_par_ok;
    cudaStream_t sb = par ? g_s1 : (cudaStream_t)0;

    CvtJob8 jw;
    jw.src[0] = h1_Wl; jw.dst[0] = wt + W_H1L; jw.n[0] = DIN * HID;
    jw.src[1] = h1_Wr; jw.dst[1] = wt + W_H1R; jw.n[1] = DIN * HID;
    jw.src[2] = h2_Wl; jw.dst[2] = wt + W_H2L; jw.n[2] = HID * HID;
    jw.src[3] = h2_Wr; jw.dst[3] = wt + W_H2R; jw.n[3] = HID * HID;
    jw.src[4] = b1_Wl; jw.dst[4] = wt + W_B1L; jw.n[4] = DIN * HID;
    jw.src[5] = b1_Wr; jw.dst[5] = wt + W_B1R; jw.n[5] = DIN * HID;
    jw.src[6] = b2_Wl; jw.dst[6] = wt + W_B2L; jw.n[6] = HID * HID;
    jw.src[7] = b2_Wr; jw.dst[7] = wt + W_B2R; jw.n[7] = HID * HID;

    if (par) {
        cudaEventRecord(g_ev_fork, 0);
        cudaStreamWaitEvent(sb, g_ev_fork, 0);
    }

    // ---- conversions on sb (overlap the CSR build on default) ----
    cvt_x_k<<<1024, TB, 0, sb>>>(x_human, xh, xhb, N * DIN);
    cvt_x_k<<<1024, TB, 0, sb>>>(x_bact, xb, xbb, N * DIN);
    cvt_w8<<<w8_grid, TB, 0, sb>>>(jw);
    if (par) cudaEventRecord(g_ev_cvt, sb);

    // ---- CSR build (default stream) ----
    cudaMemsetAsync(cnt, 0, 2 * N_NODES * sizeof(int));
    count_deg<<<nb_E, TB>>>(src, dst, cnt, E);
    scan_reduce<<<scan_grid, TB>>>(cnt, part, N);
    scan_top<<<top_grid, 512>>>(part, nb_N);
    scan_write<<<scan_grid, TB>>>(cnt, part, rowptr, cursor, N, E);
    scatter_adj<<<nb_E, TB>>>(src, dst, cursor, adj, E);

    if (par) {
        cudaEventRecord(g_ev_csr, 0);
        cudaStreamWaitEvent(sb, g_ev_csr, 0);                // bacterial branch needs CSR
        cudaStreamWaitEvent((cudaStream_t)0, g_ev_cvt, 0);   // human branch needs cvts
    }

    // ---- human branch (default stream) ----
    aggregate_csr_b16<<<nb_agg, TB>>>(xhb, rp_s, adj_s, agg, N, DIN);
    sage_gemm_pipe<<<gemm_grid, 128, GEMM_SMEM>>>(agg, xh, wt + W_H1L, wt + W_H1R, h1_b,
                                                  hid, hidb, N, DIN, 1);
    aggregate_csr_b16<<<nb_agg, TB>>>(hidb, rp_s, adj_s, agg, N, HID);
    sage_gemm_pipe<<<gemm_grid, 128, GEMM_SMEM>>>(agg, hid, wt + W_H2L, wt + W_H2R, h2_b,
                                                  hout, (__nv_bfloat16*)nullptr, N, HID, 0);

    // ---- bacterial branch (stream sb) ----
    aggregate_csr_b16<<<nb_agg, TB, 0, sb>>>(xbb, rp_d, adj_d, agg2, N, DIN);
    sage_gemm_pipe<<<gemm_grid, 128, GEMM_SMEM, sb>>>(agg2, xb, wt + W_B1L, wt + W_B1R, b1_b,
                                                      hid2, hid2b, N, DIN, 1);
    aggregate_csr_b16<<<nb_agg, TB, 0, sb>>>(hid2b, rp_d, adj_d, agg2, N, HID);
    sage_gemm_pipe<<<gemm_grid, 128, GEMM_SMEM, sb>>>(agg2, hid2, wt + W_B2L, wt + W_B2R, b2_b,
                                                      bout, (__nv_bfloat16*)nullptr, N, HID, 0);

    if (par) {
        cudaEventRecord(g_ev_join, sb);
        cudaStreamWaitEvent((cudaStream_t)0, g_ev_join, 0);
    }
}